// round 13
// baseline (speedup 1.0000x reference)
#include <cuda_runtime.h>
#include <cuda_fp16.h>
#include <math.h>
#include <stdint.h>

// ---------------- problem constants ----------------
#define BD    16
#define CC    512
#define NHD   16
#define HDIM  32
#define HID   2048
#define NN    49
#define LL    3136
#define ROWS  (BD*LL)          // 50176
#define SCALE 0.17677669529663687f

// ---------------- scratch ----------------
__device__ __half g_h  [(size_t)ROWS*CC];
__device__ __half g_q  [(size_t)ROWS*CC];
__device__ __half g_k  [(size_t)ROWS*CC];
__device__ __half g_v  [(size_t)ROWS*CC];
__device__ __half g_ao [(size_t)ROWS*CC];
__device__ float  g_x1 [(size_t)ROWS*CC];
__device__ __half g_hid[(size_t)ROWS*HID];
__device__ __half g_wqkv[(size_t)1536*CC];   // [N=1536, K=512]
__device__ __half g_w1t [(size_t)HID*CC];    // [2048, 512]
__device__ __half g_w2t [(size_t)CC*HID];    // [512, 2048]
__device__ __half g_wpt [(size_t)CC*CC];     // [512, 512]
__device__ float  g_bqkv[1536];

// ---------------- helpers ----------------
__device__ __forceinline__ uint32_t smem_u32(const void* p){
    uint32_t a; asm("{ .reg .u64 t; cvta.to.shared.u64 t, %1; cvt.u32.u64 %0, t; }" : "=r"(a) : "l"(p)); return a;
}
#define CP16(dst, src) asm volatile("cp.async.cg.shared.global [%0], [%1], 16;" :: "r"(dst), "l"(src))
#define CP_COMMIT()    asm volatile("cp.async.commit_group;" ::: "memory")
#define LDSM4(r0,r1,r2,r3,addr) \
    asm volatile("ldmatrix.sync.aligned.m8n8.x4.shared.b16 {%0,%1,%2,%3}, [%4];" \
        : "=r"(r0), "=r"(r1), "=r"(r2), "=r"(r3) : "r"(addr))
#define LDSM4T(r0,r1,r2,r3,addr) \
    asm volatile("ldmatrix.sync.aligned.m8n8.x4.trans.shared.b16 {%0,%1,%2,%3}, [%4];" \
        : "=r"(r0), "=r"(r1), "=r"(r2), "=r"(r3) : "r"(addr))

__device__ __forceinline__ void mma_f16(float* c, const uint32_t* a, const uint32_t* b){
    asm volatile("mma.sync.aligned.m16n8k16.row.col.f32.f16.f16.f32 "
        "{%0,%1,%2,%3}, {%4,%5,%6,%7}, {%8,%9}, {%0,%1,%2,%3};"
        : "+f"(c[0]), "+f"(c[1]), "+f"(c[2]), "+f"(c[3])
        : "r"(a[0]), "r"(a[1]), "r"(a[2]), "r"(a[3]), "r"(b[0]), "r"(b[1]));
}
__device__ __forceinline__ uint32_t h2u(float a, float b){
    __half2 h = __floats2half2_rn(a, b);
    return *(uint32_t*)&h;
}

// ---------------- fp16 mma.sync GEMM: CTA 128x128, 4 warps, warp tile 64x64 ----------------
#define ABYTES 16384
#define SSZB   (2*ABYTES)
#define NSTG   3

template<int MODE>
__global__ __launch_bounds__(128, 2)
void mma_gemm(const __half* __restrict__ A, const __half* __restrict__ Bt,
              const float* __restrict__ bias, const float* __restrict__ aux,
              float* __restrict__ O0,
              __half* __restrict__ Oh0, __half* __restrict__ Oh1, __half* __restrict__ Oh2,
              int K, int N)
{
    extern __shared__ float sm[];
    uint32_t smb = smem_u32(sm);

    int t    = threadIdx.x;
    int wid  = t >> 5, lane = t & 31;
    int g    = lane >> 2, tg = lane & 3;
    int wm   = (wid >> 1) * 64;        // 0 / 64
    int wn   = (wid & 1) * 64;         // 0 / 64
    int bm   = blockIdx.y << 7, bn = blockIdx.x << 7;
    int KT   = K >> 6;

    uint32_t rowA = (uint32_t)(wm + (lane & 15));
    uint32_t rbA  = rowA << 7, rxA = rowA & 7, laA = (uint32_t)(lane >> 4);
    uint32_t rowB = (uint32_t)(wn + ((lane >> 4) << 3) + (lane & 7));
    uint32_t rbB  = rowB << 7, rxB = rowB & 7, laB = (uint32_t)((lane >> 3) & 1);

    const __half* Abase = A  + (size_t)bm * K;
    const __half* Bbase = Bt + (size_t)bn * K;

    auto load_stage = [&](int st){
        uint32_t sA = smb + (uint32_t)(st % NSTG) * SSZB;
        uint32_t sB = sA + ABYTES;
        int k0 = st << 6;
        #pragma unroll
        for (int l = 0; l < 8; l++){
            int idx = l*128 + t;
            int row = idx >> 3, c = idx & 7;
            uint32_t doff = ((uint32_t)row << 7) | ((uint32_t)(c ^ (row & 7)) << 4);
            CP16(sA + doff, Abase + (size_t)row*K + k0 + c*8);
            CP16(sB + doff, Bbase + (size_t)row*K + k0 + c*8);
        }
        CP_COMMIT();
    };

    float acc[4][8][4];
    #pragma unroll
    for (int i = 0; i < 4; i++){
        #pragma unroll
        for (int j = 0; j < 8; j++){
            #pragma unroll
            for (int r = 0; r < 4; r++) acc[i][j][r] = 0.f;
        }
    }

    load_stage(0);
    load_stage(1);

    for (int kt = 0; kt < KT; kt++){
        if (kt + 1 < KT) asm volatile("cp.async.wait_group 1;" ::: "memory");
        else             asm volatile("cp.async.wait_group 0;" ::: "memory");
        __syncthreads();

        if (kt + 2 < KT) load_stage(kt + 2);

        uint32_t sA = smb + (uint32_t)(kt % NSTG) * SSZB;
        uint32_t sB = sA + ABYTES;

        #pragma unroll
        for (int kk = 0; kk < 64; kk += 16){
            uint32_t kkc = (uint32_t)(kk >> 3);
            uint32_t a[4][4], b[8][2];
            uint32_t caA = ((kkc + laA) ^ rxA) << 4;
            uint32_t caB = ((kkc + laB) ^ rxB) << 4;
            #pragma unroll
            for (int mt = 0; mt < 4; mt++)
                LDSM4(a[mt][0], a[mt][1], a[mt][2], a[mt][3],
                      sA + rbA + (uint32_t)mt*2048 + caA);
            #pragma unroll
            for (int p = 0; p < 4; p++)
                LDSM4(b[2*p][0], b[2*p][1], b[2*p+1][0], b[2*p+1][1],
                      sB + rbB + (uint32_t)p*2048 + caB);
            #pragma unroll
            for (int mt = 0; mt < 4; mt++){
                #pragma unroll
                for (int nt = 0; nt < 8; nt++)
                    mma_f16(acc[mt][nt], a[mt], b[nt]);
            }
        }
    }

    // ---------------- epilogue ----------------
    #pragma unroll
    for (int mt = 0; mt < 4; mt++){
        #pragma unroll
        for (int half_ = 0; half_ < 2; half_++){
            int r = bm + wm + mt*16 + g + half_*8;
            int win_ = 0, n_ = 0;
            if (MODE == 0){
                int b_ = r / 3136; int pos = r - b_*3136;
                int hy = pos / 56, wx = pos - hy*56;
                win_ = b_*64 + (hy/7)*8 + (wx/7);
                n_   = (hy%7)*7 + (wx%7);
            }
            #pragma unroll
            for (int nt = 0; nt < 8; nt++){
                int c = bn + wn + nt*8 + tg*2;
                float v0 = acc[mt][nt][half_*2+0] + bias[c];
                float v1 = acc[mt][nt][half_*2+1] + bias[c+1];
                if (MODE == 0){
                    int sel = c >> 9, cp = c & 511, head = cp >> 5;
                    float scl = (sel == 0) ? SCALE : 1.0f;
                    __half* dst = (sel == 0) ? Oh0 : ((sel == 1) ? Oh1 : Oh2);
                    __half* dp = dst + (((size_t)(win_*16 + head)*49 + n_) << 5) + (cp & 31);
                    *(__half2*)dp = __floats2half2_rn(v0*scl, v1*scl);
                } else if (MODE == 2){
                    __half* dp = Oh0 + (size_t)r*N + c;
                    float o0 = 0.5f*v0*(1.0f + erff(v0*0.70710678118654752f));
                    float o1 = 0.5f*v1*(1.0f + erff(v1*0.70710678118654752f));
                    *(__half2*)dp = __floats2half2_rn(o0, o1);
                } else {
                    const float* ap = aux + (size_t)r*N + c;
                    float* dp = O0 + (size_t)r*N + c;
                    float2 a2 = *(const float2*)ap;
                    *(float2*)dp = make_float2(v0 + a2.x, v1 + a2.y);
                }
            }
        }
    }
}

// ---------------- merged weight prep: 6 transposes in one launch ----------------
__global__ __launch_bounds__(256)
void transpose_all(const float* __restrict__ s0, const float* __restrict__ s1,
                   const float* __restrict__ s2, const float* __restrict__ s3,
                   const float* __restrict__ s4, const float* __restrict__ s5)
{
    __shared__ float tile[32][33];
    int z = blockIdx.z;
    const float* src; __half* dst; int K, N;
    if      (z==0){ src=s0; dst=g_wqkv;            K=512;  N=512;  }
    else if (z==1){ src=s1; dst=g_wqkv+512*512;    K=512;  N=512;  }
    else if (z==2){ src=s2; dst=g_wqkv+1024*512;   K=512;  N=512;  }
    else if (z==3){ src=s3; dst=g_wpt;             K=512;  N=512;  }
    else if (z==4){ src=s4; dst=g_w1t;             K=512;  N=2048; }
    else          { src=s5; dst=g_w2t;             K=2048; N=512;  }
    int kb = blockIdx.y*32, nb = blockIdx.x*32;
    if (kb >= K || nb >= N) return;
    int tx = threadIdx.x & 31, ty = threadIdx.x >> 5;
    #pragma unroll
    for (int i=ty;i<32;i+=8) tile[i][tx] = src[(size_t)(kb+i)*N + nb+tx];
    __syncthreads();
    #pragma unroll
    for (int i=ty;i<32;i+=8) dst[(size_t)(nb+i)*K + kb+tx] = __float2half_rn(tile[tx][i]);
}

__global__ void bias_concat(const float* bq, const float* bk, const float* bv, float* o)
{
    int i = blockIdx.x*256 + threadIdx.x;
    if (i < 512)        o[i] = bq[i];
    else if (i < 1024)  o[i] = bk[i-512];
    else if (i < 1536)  o[i] = bv[i-1024];
}

// ---------------- LayerNorm: fp32 in -> fp16 out ----------------
__global__ __launch_bounds__(128)
void ln_kernel(const float* __restrict__ x, const float* __restrict__ g,
               const float* __restrict__ b, __half* __restrict__ out)
{
    int row = blockIdx.x;
    int t = threadIdx.x;
    const float4* xr = (const float4*)(x + (size_t)row*CC);
    float4 v = xr[t];
    float s  = v.x + v.y + v.z + v.w;
    float ss = v.x*v.x + v.y*v.y + v.z*v.z + v.w*v.w;
    #pragma unroll
    for (int off = 16; off > 0; off >>= 1) {
        s  += __shfl_xor_sync(0xffffffff, s,  off);
        ss += __shfl_xor_sync(0xffffffff, ss, off);
    }
    __shared__ float sb[4], ssb[4];
    int warp = t >> 5, lane = t & 31;
    if (lane == 0) { sb[warp] = s; ssb[warp] = ss; }
    __syncthreads();
    float tot  = sb[0]+sb[1]+sb[2]+sb[3];
    float tots = ssb[0]+ssb[1]+ssb[2]+ssb[3];
    float mu   = tot * (1.0f/CC);
    float var  = tots * (1.0f/CC) - mu*mu;
    float rstd = rsqrtf(var + 1e-5f);
    float4 gv = ((const float4*)g)[t];
    float4 bv = ((const float4*)b)[t];
    __half2* o = (__half2*)(out + (size_t)row*CC);
    o[2*t+0] = __floats2half2_rn((v.x-mu)*rstd*gv.x + bv.x, (v.y-mu)*rstd*gv.y + bv.y);
    o[2*t+1] = __floats2half2_rn((v.z-mu)*rstd*gv.z + bv.z, (v.w-mu)*rstd*gv.w + bv.w);
}

// ---------------- tensor-core attention: one block per (win,head), 4 warps ----------------
#define AST 40     // smem row stride in halves (80 B)

__global__ __launch_bounds__(128)
void attn_kernel(const __half* __restrict__ q, const __half* __restrict__ k,
                 const __half* __restrict__ v, const float* __restrict__ rb,
                 __half* __restrict__ out)
{
    __shared__ __half qs[64*AST];
    __shared__ __half ks[64*AST];
    __shared__ __half vs[64*AST];

    int t = threadIdx.x, wid = t >> 5, lane = t & 31;
    int g = lane >> 2, tg = lane & 3;
    int wh = blockIdx.x, head = wh & 15;
    size_t base = (size_t)wh * (NN*HDIM);

    for (int i = t; i < 75; i += 128){
        ((uint4*)(qs + 49*AST))[i] = make_uint4(0,0,0,0);
        ((uint4*)(ks + 49*AST))[i] = make_uint4(0,0,0,0);
        ((uint4*)(vs + 49*AST))[i] = make_uint4(0,0,0,0);
    }
    for (int i = t; i < 196; i += 128){
        int row = i >> 2, c = (i & 3) << 3;
        *(uint4*)(qs + row*AST + c) = *(const uint4*)(q + base + row*32 + c);
        *(uint4*)(ks + row*AST + c) = *(const uint4*)(k + base + row*32 + c);
        *(uint4*)(vs + row*AST + c) = *(const uint4*)(v + base + row*32 + c);
    }
    __syncthreads();

    uint32_t smq = smem_u32(qs), smk = smem_u32(ks), smv = smem_u32(vs);

    uint32_t aq[2][4];
    {
        uint32_t row = (uint32_t)(wid*16 + (lane & 15));
        uint32_t a0 = smq + row*(AST*2) + ((uint32_t)(lane >> 4) << 4);
        LDSM4(aq[0][0],aq[0][1],aq[0][2],aq[0][3], a0);
        LDSM4(aq[1][0],aq[1][1],aq[1][2],aq[1][3], a0 + 32);
    }
    uint32_t bkr[4][2][4];
    {
        uint32_t row = (((uint32_t)lane >> 4) << 3) + (uint32_t)(lane & 7);
        uint32_t ck  = ((((uint32_t)lane) >> 3) & 1) << 4;
        #pragma unroll
        for (int p = 0; p < 4; p++){
            uint32_t ad = smk + ((uint32_t)(16*p) + row)*(AST*2) + ck;
            LDSM4(bkr[p][0][0],bkr[p][0][1],bkr[p][0][2],bkr[p][0][3], ad);
            LDSM4(bkr[p][1][0],bkr[p][1][1],bkr[p][1][2],bkr[p][1][3], ad + 32);
        }
    }

    float accS[7][4];
    #pragma unroll
    for (int nt = 0; nt < 7; nt++){
        accS[nt][0]=accS[nt][1]=accS[nt][2]=accS[nt][3]=0.f;
    }
    #pragma unroll
    for (int nt = 0; nt < 7; nt++){
        int p = nt >> 1, o = (nt & 1) << 1;
        mma_f16(accS[nt], aq[0], &bkr[p][0][o]);
        mma_f16(accS[nt], aq[1], &bkr[p][1][o]);
    }

    int i0 = wid*16 + g;
    int i1 = i0 + 8;
    const float* rbh = rb + (size_t)head*(NN*NN);
    #pragma unroll
    for (int nt = 0; nt < 7; nt++){
        int j0 = nt*8 + tg*2;
        if (i0 < NN){
            accS[nt][0] = (j0   < NN) ? accS[nt][0] + rbh[i0*NN + j0]   : -1e30f;
            accS[nt][1] = (j0+1 < NN) ? accS[nt][1] + rbh[i0*NN + j0+1] : -1e30f;
        } else { accS[nt][0] = 0.f; accS[nt][1] = 0.f; }
        if (i1 < NN){
            accS[nt][2] = (j0   < NN) ? accS[nt][2] + rbh[i1*NN + j0]   : -1e30f;
            accS[nt][3] = (j0+1 < NN) ? accS[nt][3] + rbh[i1*NN + j0+1] : -1e30f;
        } else { accS[nt][2] = 0.f; accS[nt][3] = 0.f; }
    }

    float m0 = -1e30f, m1 = -1e30f;
    #pragma unroll
    for (int nt = 0; nt < 7; nt++){
        m0 = fmaxf(m0, fmaxf(accS[nt][0], accS[nt][1]));
        m1 = fmaxf(m1, fmaxf(accS[nt][2], accS[nt][3]));
    }
    m0 = fmaxf(m0, __shfl_xor_sync(0xffffffff, m0, 1));
    m0 = fmaxf(m0, __shfl_xor_sync(0xffffffff, m0, 2));
    m1 = fmaxf(m1, __shfl_xor_sync(0xffffffff, m1, 1));
    m1 = fmaxf(m1, __shfl_xor_sync(0xffffffff, m1, 2));
    float s0 = 0.f, s1 = 0.f;
    #pragma unroll
    for (int nt = 0; nt < 7; nt++){
        accS[nt][0] = __expf(accS[nt][0] - m0);
        accS[nt][1] = __expf(accS[nt][1] - m0);
        accS[nt][2] = __expf(accS[nt][2] - m1);
        accS[nt][3] = __expf(accS[nt][3] - m1);
        s0 += accS[nt][0] + accS[nt][1];
        s1 += accS[nt][2] + accS[nt][3];
    }
    s0 += __shfl_xor_sync(0xffffffff, s0, 1);
    s0 += __shfl_xor_sync(0xffffffff, s0, 2);
    s1 += __shfl_xor_sync(0xffffffff, s1, 1);
    s1 += __shfl_xor_sync(0xffffffff, s1, 2);
    float inv0 = __frcp_rn(s0), inv1 = __frcp_rn(s1);

    float accO[4][4];
    #pragma unroll
    for (int nt = 0; nt < 4; nt++){
        accO[nt][0]=accO[nt][1]=accO[nt][2]=accO[nt][3]=0.f;
    }
    uint32_t rowv = ((((uint32_t)lane) >> 3) & 1) * 8 + (uint32_t)(lane & 7);
    uint32_t cv   = ((uint32_t)(lane >> 4)) << 4;
    #pragma unroll
    for (int kt = 0; kt < 4; kt++){
        uint32_t ap[4];
        int ntl = 2*kt;
        ap[0] = h2u(accS[ntl][0]*inv0, accS[ntl][1]*inv0);
        ap[1] = h2u(accS[ntl][2]*inv1, accS[ntl][3]*inv1);
        if (kt < 3){
            ap[2] = h2u(accS[ntl+1][0]*inv0, accS[ntl+1][1]*inv0);
            ap[3] = h2u(accS[ntl+1][2]*inv1, accS[ntl+1][3]*inv1);
        } else { ap[2] = 0u; ap[3] = 0u; }

        uint32_t bv[8];
        uint32_t ad = smv + ((uint32_t)(16*kt) + rowv)*(AST*2) + cv;
        LDSM4T(bv[0],bv[1],bv[2],bv[3], ad);
        LDSM4T(bv[4],bv[5],bv[6],bv[7], ad + 32);
        mma_f16(accO[0], ap, &bv[0]);
        mma_f16(accO[1], ap, &bv[2]);
        mma_f16(accO[2], ap, &bv[4]);
        mma_f16(accO[3], ap, &bv[6]);
    }

    int win = wh >> 4;
    int b_ = win >> 6, wy = (win & 63) >> 3, wx = win & 7;
    if (i0 < NN){
        int iy = i0 / 7, ix = i0 - iy*7;
        int r = b_*3136 + (wy*7 + iy)*56 + wx*7 + ix;
        __half* dp = out + (size_t)r*CC + head*HDIM;
        #pragma unroll
        for (int nt = 0; nt < 4; nt++)
            *(__half2*)(dp + nt*8 + tg*2) = __floats2half2_rn(accO[nt][0], accO[nt][1]);
    }
    if (i1 < NN){
        int iy = i1 / 7, ix = i1 - iy*7;
        int r = b_*3136 + (wy*7 + iy)*56 + wx*7 + ix;
        __half* dp = out + (size_t)r*CC + head*HDIM;
        #pragma unroll
        for (int nt = 0; nt < 4; nt++)
            *(__half2*)(dp + nt*8 + tg*2) = __floats2half2_rn(accO[nt][2], accO[nt][3]);
    }
}

// ---------------- launch ----------------
extern "C" void kernel_launch(void* const* d_in, const int* in_sizes, int n_in,
                              void* d_out, int out_size)
{
    const float* x    = (const float*)d_in[0];
    const float* Wq   = (const float*)d_in[1];
    const float* bq   = (const float*)d_in[2];
    const float* Wk   = (const float*)d_in[3];
    const float* bk   = (const float*)d_in[4];
    const float* Wv   = (const float*)d_in[5];
    const float* bv   = (const float*)d_in[6];
    const float* Wp   = (const float*)d_in[7];
    const float* bp   = (const float*)d_in[8];
    const float* rb   = (const float*)d_in[9];
    const float* g1   = (const float*)d_in[10];
    const float* b1   = (const float*)d_in[11];
    const float* g2   = (const float*)d_in[12];
    const float* b2   = (const float*)d_in[13];
    const float* W1   = (const float*)d_in[14];
    const float* bfc1 = (const float*)d_in[15];
    const float* W2   = (const float*)d_in[16];
    const float* bfc2 = (const float*)d_in[17];
    float* out = (float*)d_out;

    __half *h,*q,*k,*v,*ao,*hid,*wqkv,*w1t,*w2t,*wpt;
    float *x1,*bqkv;
    cudaGetSymbolAddress((void**)&h,    g_h);
    cudaGetSymbolAddress((void**)&q,    g_q);
    cudaGetSymbolAddress((void**)&k,    g_k);
    cudaGetSymbolAddress((void**)&v,    g_v);
    cudaGetSymbolAddress((void**)&ao,   g_ao);
    cudaGetSymbolAddress((void**)&x1,   g_x1);
    cudaGetSymbolAddress((void**)&hid,  g_hid);
    cudaGetSymbolAddress((void**)&wqkv, g_wqkv);
    cudaGetSymbolAddress((void**)&w1t,  g_w1t);
    cudaGetSymbolAddress((void**)&w2t,  g_w2t);
    cudaGetSymbolAddress((void**)&wpt,  g_wpt);
    cudaGetSymbolAddress((void**)&bqkv, g_bqkv);

    int shb = NSTG * SSZB;   // 98304 B
    cudaFuncSetAttribute(mma_gemm<0>, cudaFuncAttributeMaxDynamicSharedMemorySize, shb);
    cudaFuncSetAttribute(mma_gemm<1>, cudaFuncAttributeMaxDynamicSharedMemorySize, shb);
    cudaFuncSetAttribute(mma_gemm<2>, cudaFuncAttributeMaxDynamicSharedMemorySize, shb);
    cudaFuncSetAttribute(mma_gemm<3>, cudaFuncAttributeMaxDynamicSharedMemorySize, shb);

    transpose_all<<<dim3(64,64,6),256>>>(Wq, Wk, Wv, Wp, W1, W2);
    bias_concat<<<6,256>>>(bq, bk, bv, bqkv);
    ln_kernel<<<ROWS,128>>>(x, g1, b1, h);
    mma_gemm<0><<<dim3(12,392),128,shb>>>(h, wqkv, bqkv, nullptr, nullptr, q, k, v, 512, 1536);
    attn_kernel<<<BD*64*NHD,128>>>(q, k, v, rb, ao);
    mma_gemm<1><<<dim3(4,392),128,shb>>>(ao, wpt, bp, x, x1, nullptr, nullptr, nullptr, 512, 512);
    ln_kernel<<<ROWS,128>>>(x1, g2, b2, h);
    mma_gemm<2><<<dim3(16,392),128,shb>>>(h, w1t, bfc1, nullptr, nullptr, hid, nullptr, nullptr, 512, HID);
    mma_gemm<3><<<dim3(4,392),128,shb>>>(hid, w2t, bfc2, x1, out, nullptr, nullptr, nullptr, HID, 512);
}

// round 15
// speedup vs baseline: 1.5125x; 1.5125x over previous
#include <cuda_runtime.h>
#include <cuda_fp16.h>
#include <math.h>
#include <stdint.h>

// ---------------- problem constants ----------------
#define BD    16
#define CC    512
#define NHD   16
#define HDIM  32
#define HID   2048
#define NN    49
#define LL    3136
#define ROWS  (BD*LL)          // 50176
#define SCALE 0.17677669529663687f

// ---------------- scratch ----------------
__device__ __half g_h  [(size_t)ROWS*CC];
__device__ __half g_q  [(size_t)ROWS*CC];
__device__ __half g_k  [(size_t)ROWS*CC];
__device__ __half g_v  [(size_t)ROWS*CC];
__device__ __half g_ao [(size_t)ROWS*CC];
__device__ float  g_x1 [(size_t)ROWS*CC];
__device__ __half g_hid[(size_t)ROWS*HID];
__device__ __half g_wqkv[(size_t)1536*CC];   // [N=1536, K=512]
__device__ __half g_w1t [(size_t)HID*CC];    // [2048, 512]
__device__ __half g_w2t [(size_t)CC*HID];    // [512, 2048]
__device__ __half g_wpt [(size_t)CC*CC];     // [512, 512]
__device__ float  g_bqkv[1536];

// ---------------- helpers ----------------
__device__ __forceinline__ uint32_t smem_u32(const void* p){
    uint32_t a; asm("{ .reg .u64 t; cvta.to.shared.u64 t, %1; cvt.u32.u64 %0, t; }" : "=r"(a) : "l"(p)); return a;
}
#define CP16(dst, src) asm volatile("cp.async.cg.shared.global [%0], [%1], 16;" :: "r"(dst), "l"(src))
#define CP_COMMIT()    asm volatile("cp.async.commit_group;" ::: "memory")
#define LDSM4(r0,r1,r2,r3,addr) \
    asm volatile("ldmatrix.sync.aligned.m8n8.x4.shared.b16 {%0,%1,%2,%3}, [%4];" \
        : "=r"(r0), "=r"(r1), "=r"(r2), "=r"(r3) : "r"(addr))
#define LDSM4T(r0,r1,r2,r3,addr) \
    asm volatile("ldmatrix.sync.aligned.m8n8.x4.trans.shared.b16 {%0,%1,%2,%3}, [%4];" \
        : "=r"(r0), "=r"(r1), "=r"(r2), "=r"(r3) : "r"(addr))

__device__ __forceinline__ void mma_f16(float* c, const uint32_t* a, const uint32_t* b){
    asm volatile("mma.sync.aligned.m16n8k16.row.col.f32.f16.f16.f32 "
        "{%0,%1,%2,%3}, {%4,%5,%6,%7}, {%8,%9}, {%0,%1,%2,%3};"
        : "+f"(c[0]), "+f"(c[1]), "+f"(c[2]), "+f"(c[3])
        : "r"(a[0]), "r"(a[1]), "r"(a[2]), "r"(a[3]), "r"(b[0]), "r"(b[1]));
}
__device__ __forceinline__ uint32_t h2u(float a, float b){
    __half2 h = __floats2half2_rn(a, b);
    return *(uint32_t*)&h;
}

// ---------------- fp16 mma.sync GEMM: CTA 128x128, 8 warps (2M x 4N), warp tile 64x32 ----------------
#define ABYTES 16384
#define SSZB   (2*ABYTES)
#define NSTG   3

template<int MODE>
__global__ __launch_bounds__(256, 2)
void mma_gemm(const __half* __restrict__ A, const __half* __restrict__ Bt,
              const float* __restrict__ bias, const float* __restrict__ aux,
              float* __restrict__ O0,
              __half* __restrict__ Oh0, __half* __restrict__ Oh1, __half* __restrict__ Oh2,
              int K, int N)
{
    extern __shared__ float sm[];
    uint32_t smb = smem_u32(sm);

    int t    = threadIdx.x;
    int wid  = t >> 5, lane = t & 31;
    int g    = lane >> 2, tg = lane & 3;
    int wm   = (wid >> 2) * 64;
    int wn   = (wid & 3) * 32;
    int bm   = blockIdx.y << 7, bn = blockIdx.x << 7;
    int KT   = K >> 6;

    uint32_t rowA = (uint32_t)(wm + (lane & 15));
    uint32_t rbA  = rowA << 7, rxA = rowA & 7, laA = (uint32_t)(lane >> 4);
    uint32_t rowB = (uint32_t)(wn + ((lane >> 4) << 3) + (lane & 7));
    uint32_t rbB  = rowB << 7, rxB = rowB & 7, laB = (uint32_t)((lane >> 3) & 1);

    const __half* Abase = A  + (size_t)bm * K;
    const __half* Bbase = Bt + (size_t)bn * K;

    auto load_stage = [&](int st){
        uint32_t sA = smb + (uint32_t)(st % NSTG) * SSZB;
        uint32_t sB = sA + ABYTES;
        int k0 = st << 6;
        #pragma unroll
        for (int l = 0; l < 4; l++){
            int idx = l*256 + t;
            int row = idx >> 3, c = idx & 7;
            uint32_t doff = ((uint32_t)row << 7) | ((uint32_t)(c ^ (row & 7)) << 4);
            CP16(sA + doff, Abase + (size_t)row*K + k0 + c*8);
            CP16(sB + doff, Bbase + (size_t)row*K + k0 + c*8);
        }
        CP_COMMIT();
    };

    float acc[4][4][4];
    #pragma unroll
    for (int i = 0; i < 4; i++){
        #pragma unroll
        for (int j = 0; j < 4; j++){
            #pragma unroll
            for (int r = 0; r < 4; r++) acc[i][j][r] = 0.f;
        }
    }

    load_stage(0);
    load_stage(1);

    for (int kt = 0; kt < KT; kt++){
        if (kt + 1 < KT) asm volatile("cp.async.wait_group 1;" ::: "memory");
        else             asm volatile("cp.async.wait_group 0;" ::: "memory");
        __syncthreads();

        uint32_t sA = smb + (uint32_t)(kt % NSTG) * SSZB;
        uint32_t sB = sA + ABYTES;

        #pragma unroll
        for (int kk = 0; kk < 64; kk += 16){
            uint32_t kkc = (uint32_t)(kk >> 3);
            uint32_t a[4][4], b[4][2];
            uint32_t caA = ((kkc + laA) ^ rxA) << 4;
            uint32_t caB = ((kkc + laB) ^ rxB) << 4;
            #pragma unroll
            for (int mt = 0; mt < 4; mt++)
                LDSM4(a[mt][0], a[mt][1], a[mt][2], a[mt][3],
                      sA + rbA + (uint32_t)mt*2048 + caA);
            LDSM4(b[0][0], b[0][1], b[1][0], b[1][1], sB + rbB + caB);
            LDSM4(b[2][0], b[2][1], b[3][0], b[3][1], sB + rbB + 2048 + caB);
            #pragma unroll
            for (int mt = 0; mt < 4; mt++){
                #pragma unroll
                for (int nt = 0; nt < 4; nt++)
                    mma_f16(acc[mt][nt], a[mt], b[nt]);
            }
            // issue next-stage prefetch after the first slab's work is queued:
            // LDSMs for slab 0 go out immediately post-barrier; cp.async has a
            // full kt of slack (3-stage ring), so moving it off the critical
            // path shortens the post-barrier stall.
            if (kk == 0 && kt + 2 < KT) load_stage(kt + 2);
        }
    }

    // ---------------- epilogue ----------------
    #pragma unroll
    for (int mt = 0; mt < 4; mt++){
        #pragma unroll
        for (int half_ = 0; half_ < 2; half_++){
            int r = bm + wm + mt*16 + g + half_*8;
            int win_ = 0, n_ = 0;
            if (MODE == 0){
                int b_ = r / 3136; int pos = r - b_*3136;
                int hy = pos / 56, wx = pos - hy*56;
                win_ = b_*64 + (hy/7)*8 + (wx/7);
                n_   = (hy%7)*7 + (wx%7);
            }
            #pragma unroll
            for (int nt = 0; nt < 4; nt++){
                int c = bn + wn + nt*8 + tg*2;
                float v0 = acc[mt][nt][half_*2+0] + bias[c];
                float v1 = acc[mt][nt][half_*2+1] + bias[c+1];
                if (MODE == 0){
                    int sel = c >> 9, cp = c & 511, head = cp >> 5;
                    float scl = (sel == 0) ? SCALE : 1.0f;
                    __half* dst = (sel == 0) ? Oh0 : ((sel == 1) ? Oh1 : Oh2);
                    __half* dp = dst + (((size_t)(win_*16 + head)*49 + n_) << 5) + (cp & 31);
                    *(__half2*)dp = __floats2half2_rn(v0*scl, v1*scl);
                } else if (MODE == 2){
                    __half* dp = Oh0 + (size_t)r*N + c;
                    float o0 = 0.5f*v0*(1.0f + erff(v0*0.70710678118654752f));
                    float o1 = 0.5f*v1*(1.0f + erff(v1*0.70710678118654752f));
                    *(__half2*)dp = __floats2half2_rn(o0, o1);
                } else {
                    const float* ap = aux + (size_t)r*N + c;
                    float* dp = O0 + (size_t)r*N + c;
                    float2 a2 = *(const float2*)ap;
                    *(float2*)dp = make_float2(v0 + a2.x, v1 + a2.y);
                }
            }
        }
    }
}

// ---------------- merged weight prep: 6 transposes in one launch ----------------
__global__ __launch_bounds__(256)
void transpose_all(const float* __restrict__ s0, const float* __restrict__ s1,
                   const float* __restrict__ s2, const float* __restrict__ s3,
                   const float* __restrict__ s4, const float* __restrict__ s5)
{
    __shared__ float tile[32][33];
    int z = blockIdx.z;
    const float* src; __half* dst; int K, N;
    if      (z==0){ src=s0; dst=g_wqkv;            K=512;  N=512;  }
    else if (z==1){ src=s1; dst=g_wqkv+512*512;    K=512;  N=512;  }
    else if (z==2){ src=s2; dst=g_wqkv+1024*512;   K=512;  N=512;  }
    else if (z==3){ src=s3; dst=g_wpt;             K=512;  N=512;  }
    else if (z==4){ src=s4; dst=g_w1t;             K=512;  N=2048; }
    else          { src=s5; dst=g_w2t;             K=2048; N=512;  }
    int kb = blockIdx.y*32, nb = blockIdx.x*32;
    if (kb >= K || nb >= N) return;
    int tx = threadIdx.x & 31, ty = threadIdx.x >> 5;
    #pragma unroll
    for (int i=ty;i<32;i+=8) tile[i][tx] = src[(size_t)(kb+i)*N + nb+tx];
    __syncthreads();
    #pragma unroll
    for (int i=ty;i<32;i+=8) dst[(size_t)(nb+i)*K + kb+tx] = __float2half_rn(tile[tx][i]);
}

__global__ void bias_concat(const float* bq, const float* bk, const float* bv, float* o)
{
    int i = blockIdx.x*256 + threadIdx.x;
    if (i < 512)        o[i] = bq[i];
    else if (i < 1024)  o[i] = bk[i-512];
    else if (i < 1536)  o[i] = bv[i-1024];
}

// ---------------- LayerNorm: fp32 in -> fp16 out ----------------
__global__ __launch_bounds__(128)
void ln_kernel(const float* __restrict__ x, const float* __restrict__ g,
               const float* __restrict__ b, __half* __restrict__ out)
{
    int row = blockIdx.x;
    int t = threadIdx.x;
    const float4* xr = (const float4*)(x + (size_t)row*CC);
    float4 v = xr[t];
    float s  = v.x + v.y + v.z + v.w;
    float ss = v.x*v.x + v.y*v.y + v.z*v.z + v.w*v.w;
    #pragma unroll
    for (int off = 16; off > 0; off >>= 1) {
        s  += __shfl_xor_sync(0xffffffff, s,  off);
        ss += __shfl_xor_sync(0xffffffff, ss, off);
    }
    __shared__ float sb[4], ssb[4];
    int warp = t >> 5, lane = t & 31;
    if (lane == 0) { sb[warp] = s; ssb[warp] = ss; }
    __syncthreads();
    float tot  = sb[0]+sb[1]+sb[2]+sb[3];
    float tots = ssb[0]+ssb[1]+ssb[2]+ssb[3];
    float mu   = tot * (1.0f/CC);
    float var  = tots * (1.0f/CC) - mu*mu;
    float rstd = rsqrtf(var + 1e-5f);
    float4 gv = ((const float4*)g)[t];
    float4 bv = ((const float4*)b)[t];
    __half2* o = (__half2*)(out + (size_t)row*CC);
    o[2*t+0] = __floats2half2_rn((v.x-mu)*rstd*gv.x + bv.x, (v.y-mu)*rstd*gv.y + bv.y);
    o[2*t+1] = __floats2half2_rn((v.z-mu)*rstd*gv.z + bv.z, (v.w-mu)*rstd*gv.w + bv.w);
}

// ---------------- tensor-core attention: one block per (win,head), 4 warps ----------------
#define AST 40     // smem row stride in halves (80 B)

__global__ __launch_bounds__(128)
void attn_kernel(const __half* __restrict__ q, const __half* __restrict__ k,
                 const __half* __restrict__ v, const float* __restrict__ rb,
                 __half* __restrict__ out)
{
    __shared__ __half qs[64*AST];
    __shared__ __half ks[64*AST];
    __shared__ __half vs[64*AST];

    int t = threadIdx.x, wid = t >> 5, lane = t & 31;
    int g = lane >> 2, tg = lane & 3;
    int wh = blockIdx.x, head = wh & 15;
    size_t base = (size_t)wh * (NN*HDIM);

    for (int i = t; i < 75; i += 128){
        ((uint4*)(qs + 49*AST))[i] = make_uint4(0,0,0,0);
        ((uint4*)(ks + 49*AST))[i] = make_uint4(0,0,0,0);
        ((uint4*)(vs + 49*AST))[i] = make_uint4(0,0,0,0);
    }
    for (int i = t; i < 196; i += 128){
        int row = i >> 2, c = (i & 3) << 3;
        *(uint4*)(qs + row*AST + c) = *(const uint4*)(q + base + row*32 + c);
        *(uint4*)(ks + row*AST + c) = *(const uint4*)(k + base + row*32 + c);
        *(uint4*)(vs + row*AST + c) = *(const uint4*)(v + base + row*32 + c);
    }
    __syncthreads();

    uint32_t smq = smem_u32(qs), smk = smem_u32(ks), smv = smem_u32(vs);

    uint32_t aq[2][4];
    {
        uint32_t row = (uint32_t)(wid*16 + (lane & 15));
        uint32_t a0 = smq + row*(AST*2) + ((uint32_t)(lane >> 4) << 4);
        LDSM4(aq[0][0],aq[0][1],aq[0][2],aq[0][3], a0);
        LDSM4(aq[1][0],aq[1][1],aq[1][2],aq[1][3], a0 + 32);
    }
    uint32_t bkr[4][2][4];
    {
        uint32_t row = (((uint32_t)lane >> 4) << 3) + (uint32_t)(lane & 7);
        uint32_t ck  = ((((uint32_t)lane) >> 3) & 1) << 4;
        #pragma unroll
        for (int p = 0; p < 4; p++){
            uint32_t ad = smk + ((uint32_t)(16*p) + row)*(AST*2) + ck;
            LDSM4(bkr[p][0][0],bkr[p][0][1],bkr[p][0][2],bkr[p][0][3], ad);
            LDSM4(bkr[p][1][0],bkr[p][1][1],bkr[p][1][2],bkr[p][1][3], ad + 32);
        }
    }

    float accS[7][4];
    #pragma unroll
    for (int nt = 0; nt < 7; nt++){
        accS[nt][0]=accS[nt][1]=accS[nt][2]=accS[nt][3]=0.f;
    }
    #pragma unroll
    for (int nt = 0; nt < 7; nt++){
        int p = nt >> 1, o = (nt & 1) << 1;
        mma_f16(accS[nt], aq[0], &bkr[p][0][o]);
        mma_f16(accS[nt], aq[1], &bkr[p][1][o]);
    }

    int i0 = wid*16 + g;
    int i1 = i0 + 8;
    const float* rbh = rb + (size_t)head*(NN*NN);
    #pragma unroll
    for (int nt = 0; nt < 7; nt++){
        int j0 = nt*8 + tg*2;
        if (i0 < NN){
            accS[nt][0] = (j0   < NN) ? accS[nt][0] + rbh[i0*NN + j0]   : -1e30f;
            accS[nt][1] = (j0+1 < NN) ? accS[nt][1] + rbh[i0*NN + j0+1] : -1e30f;
        } else { accS[nt][0] = 0.f; accS[nt][1] = 0.f; }
        if (i1 < NN){
            accS[nt][2] = (j0   < NN) ? accS[nt][2] + rbh[i1*NN + j0]   : -1e30f;
            accS[nt][3] = (j0+1 < NN) ? accS[nt][3] + rbh[i1*NN + j0+1] : -1e30f;
        } else { accS[nt][2] = 0.f; accS[nt][3] = 0.f; }
    }

    float m0 = -1e30f, m1 = -1e30f;
    #pragma unroll
    for (int nt = 0; nt < 7; nt++){
        m0 = fmaxf(m0, fmaxf(accS[nt][0], accS[nt][1]));
        m1 = fmaxf(m1, fmaxf(accS[nt][2], accS[nt][3]));
    }
    m0 = fmaxf(m0, __shfl_xor_sync(0xffffffff, m0, 1));
    m0 = fmaxf(m0, __shfl_xor_sync(0xffffffff, m0, 2));
    m1 = fmaxf(m1, __shfl_xor_sync(0xffffffff, m1, 1));
    m1 = fmaxf(m1, __shfl_xor_sync(0xffffffff, m1, 2));
    float s0 = 0.f, s1 = 0.f;
    #pragma unroll
    for (int nt = 0; nt < 7; nt++){
        accS[nt][0] = __expf(accS[nt][0] - m0);
        accS[nt][1] = __expf(accS[nt][1] - m0);
        accS[nt][2] = __expf(accS[nt][2] - m1);
        accS[nt][3] = __expf(accS[nt][3] - m1);
        s0 += accS[nt][0] + accS[nt][1];
        s1 += accS[nt][2] + accS[nt][3];
    }
    s0 += __shfl_xor_sync(0xffffffff, s0, 1);
    s0 += __shfl_xor_sync(0xffffffff, s0, 2);
    s1 += __shfl_xor_sync(0xffffffff, s1, 1);
    s1 += __shfl_xor_sync(0xffffffff, s1, 2);
    float inv0 = __frcp_rn(s0), inv1 = __frcp_rn(s1);

    float accO[4][4];
    #pragma unroll
    for (int nt = 0; nt < 4; nt++){
        accO[nt][0]=accO[nt][1]=accO[nt][2]=accO[nt][3]=0.f;
    }
    uint32_t rowv = ((((uint32_t)lane) >> 3) & 1) * 8 + (uint32_t)(lane & 7);
    uint32_t cv   = ((uint32_t)(lane >> 4)) << 4;
    #pragma unroll
    for (int kt = 0; kt < 4; kt++){
        uint32_t ap[4];
        int ntl = 2*kt;
        ap[0] = h2u(accS[ntl][0]*inv0, accS[ntl][1]*inv0);
        ap[1] = h2u(accS[ntl][2]*inv1, accS[ntl][3]*inv1);
        if (kt < 3){
            ap[2] = h2u(accS[ntl+1][0]*inv0, accS[ntl+1][1]*inv0);
            ap[3] = h2u(accS[ntl+1][2]*inv1, accS[ntl+1][3]*inv1);
        } else { ap[2] = 0u; ap[3] = 0u; }

        uint32_t bv[8];
        uint32_t ad = smv + ((uint32_t)(16*kt) + rowv)*(AST*2) + cv;
        LDSM4T(bv[0],bv[1],bv[2],bv[3], ad);
        LDSM4T(bv[4],bv[5],bv[6],bv[7], ad + 32);
        mma_f16(accO[0], ap, &bv[0]);
        mma_f16(accO[1], ap, &bv[2]);
        mma_f16(accO[2], ap, &bv[4]);
        mma_f16(accO[3], ap, &bv[6]);
    }

    int win = wh >> 4;
    int b_ = win >> 6, wy = (win & 63) >> 3, wx = win & 7;
    if (i0 < NN){
        int iy = i0 / 7, ix = i0 - iy*7;
        int r = b_*3136 + (wy*7 + iy)*56 + wx*7 + ix;
        __half* dp = out + (size_t)r*CC + head*HDIM;
        #pragma unroll
        for (int nt = 0; nt < 4; nt++)
            *(__half2*)(dp + nt*8 + tg*2) = __floats2half2_rn(accO[nt][0], accO[nt][1]);
    }
    if (i1 < NN){
        int iy = i1 / 7, ix = i1 - iy*7;
        int r = b_*3136 + (wy*7 + iy)*56 + wx*7 + ix;
        __half* dp = out + (size_t)r*CC + head*HDIM;
        #pragma unroll
        for (int nt = 0; nt < 4; nt++)
            *(__half2*)(dp + nt*8 + tg*2) = __floats2half2_rn(accO[nt][2], accO[nt][3]);
    }
}

// ---------------- launch ----------------
extern "C" void kernel_launch(void* const* d_in, const int* in_sizes, int n_in,
                              void* d_out, int out_size)
{
    const float* x    = (const float*)d_in[0];
    const float* Wq   = (const float*)d_in[1];
    const float* bq   = (const float*)d_in[2];
    const float* Wk   = (const float*)d_in[3];
    const float* bk   = (const float*)d_in[4];
    const float* Wv   = (const float*)d_in[5];
    const float* bv   = (const float*)d_in[6];
    const float* Wp   = (const float*)d_in[7];
    const float* bp   = (const float*)d_in[8];
    const float* rb   = (const float*)d_in[9];
    const float* g1   = (const float*)d_in[10];
    const float* b1   = (const float*)d_in[11];
    const float* g2   = (const float*)d_in[12];
    const float* b2   = (const float*)d_in[13];
    const float* W1   = (const float*)d_in[14];
    const float* bfc1 = (const float*)d_in[15];
    const float* W2   = (const float*)d_in[16];
    const float* bfc2 = (const float*)d_in[17];
    float* out = (float*)d_out;

    __half *h,*q,*k,*v,*ao,*hid,*wqkv,*w1t,*w2t,*wpt;
    float *x1,*bqkv;
    cudaGetSymbolAddress((void**)&h,    g_h);
    cudaGetSymbolAddress((void**)&q,    g_q);
    cudaGetSymbolAddress((void**)&k,    g_k);
    cudaGetSymbolAddress((void**)&v,    g_v);
    cudaGetSymbolAddress((void**)&ao,   g_ao);
    cudaGetSymbolAddress((void**)&x1,   g_x1);
    cudaGetSymbolAddress((void**)&hid,  g_hid);
    cudaGetSymbolAddress((void**)&wqkv, g_wqkv);
    cudaGetSymbolAddress((void**)&w1t,  g_w1t);
    cudaGetSymbolAddress((void**)&w2t,  g_w2t);
    cudaGetSymbolAddress((void**)&wpt,  g_wpt);
    cudaGetSymbolAddress((void**)&bqkv, g_bqkv);

    int shb = NSTG * SSZB;   // 98304 B
    cudaFuncSetAttribute(mma_gemm<0>, cudaFuncAttributeMaxDynamicSharedMemorySize, shb);
    cudaFuncSetAttribute(mma_gemm<1>, cudaFuncAttributeMaxDynamicSharedMemorySize, shb);
    cudaFuncSetAttribute(mma_gemm<2>, cudaFuncAttributeMaxDynamicSharedMemorySize, shb);
    cudaFuncSetAttribute(mma_gemm<3>, cudaFuncAttributeMaxDynamicSharedMemorySize, shb);

    transpose_all<<<dim3(64,64,6),256>>>(Wq, Wk, Wv, Wp, W1, W2);
    bias_concat<<<6,256>>>(bq, bk, bv, bqkv);
    ln_kernel<<<ROWS,128>>>(x, g1, b1, h);
    mma_gemm<0><<<dim3(12,392),256,shb>>>(h, wqkv, bqkv, nullptr, nullptr, q, k, v, 512, 1536);
    attn_kernel<<<BD*64*NHD,128>>>(q, k, v, rb, ao);
    mma_gemm<1><<<dim3(4,392),256,shb>>>(ao, wpt, bp, x, x1, nullptr, nullptr, nullptr, 512, 512);
    ln_kernel<<<ROWS,128>>>(x1, g2, b2, h);
    mma_gemm<2><<<dim3(16,392),256,shb>>>(h, w1t, bfc1, nullptr, nullptr, hid, nullptr, nullptr, 512, HID);
    mma_gemm<3><<<dim3(4,392),256,shb>>>(hid, w2t, bfc2, x1, out, nullptr, nullptr, nullptr, HID, 512);
}